// round 3
// baseline (speedup 1.0000x reference)
#include <cuda_runtime.h>
#include <cstdint>

// Problem shape (fixed by setup_inputs)
#define D_IN   2048
#define D_SAE  16384
#define NROWS  8192
#define KTOP   64

// Scratch (static device globals -- allocation-free per harness rules)
__device__ float g_pre[(size_t)NROWS * D_SAE];   // 512 MB pre-activations
__device__ int   g_idx[NROWS * KTOP];
__device__ float g_val[NROWS * KTOP];

// ---------------------------------------------------------------------------
// K1: fp32 SGEMM  C = A @ B + bias
//     A = x      [M, K]  row-major (M=8192, K=2048)
//     B = W_enc  [K, N]  row-major (N=16384)
//     C = g_pre  [M, N]
// 128x128 block tile, BK=16, 256 threads, 8x8 per-thread micro-tile.
// ---------------------------------------------------------------------------
#define BM 128
#define BN 128
#define BK 16
#define TM 8
#define TN 8

__global__ __launch_bounds__(256) void sgemm_bias_kernel(
    const float* __restrict__ A,
    const float* __restrict__ B,
    const float* __restrict__ bias,
    int M, int N, int K)
{
    __shared__ float As[BK][BM];
    __shared__ float Bs[BK][BN];

    const int bx = blockIdx.x;   // n tile
    const int by = blockIdx.y;   // m tile
    const int tid = threadIdx.x;
    const int ty = tid >> 4;     // 0..15
    const int tx = tid & 15;     // 0..15

    const float* Ablk = A + (size_t)by * BM * K;
    const float* Bblk = B + (size_t)bx * BN;

    float acc[TM][TN];
    #pragma unroll
    for (int i = 0; i < TM; i++)
        #pragma unroll
        for (int j = 0; j < TN; j++)
            acc[i][j] = 0.0f;

    // Global->shared load indices
    const int arow = tid >> 2;          // 0..63 (and +64)
    const int acol = (tid & 3) * 4;     // 0,4,8,12
    const int brow = tid >> 5;          // 0..7 (and +8)
    const int bcol = (tid & 31) * 4;    // 0..124

    for (int k0 = 0; k0 < K; k0 += BK) {
        // A tile: 128 rows x 16 k, stored transposed As[k][m]
        float4 a0 = *(const float4*)(Ablk + (size_t)arow * K + k0 + acol);
        float4 a1 = *(const float4*)(Ablk + (size_t)(arow + 64) * K + k0 + acol);
        As[acol + 0][arow] = a0.x;
        As[acol + 1][arow] = a0.y;
        As[acol + 2][arow] = a0.z;
        As[acol + 3][arow] = a0.w;
        As[acol + 0][arow + 64] = a1.x;
        As[acol + 1][arow + 64] = a1.y;
        As[acol + 2][arow + 64] = a1.z;
        As[acol + 3][arow + 64] = a1.w;

        // B tile: 16 k x 128 n, stored direct Bs[k][n]
        float4 b0 = *(const float4*)(Bblk + (size_t)(k0 + brow) * N + bcol);
        float4 b1 = *(const float4*)(Bblk + (size_t)(k0 + brow + 8) * N + bcol);
        *(float4*)&Bs[brow][bcol]     = b0;
        *(float4*)&Bs[brow + 8][bcol] = b1;

        __syncthreads();

        #pragma unroll
        for (int kk = 0; kk < BK; kk++) {
            float a[TM], b[TN];
            *(float4*)&a[0] = *(const float4*)&As[kk][ty * TM];
            *(float4*)&a[4] = *(const float4*)&As[kk][ty * TM + 4];
            *(float4*)&b[0] = *(const float4*)&Bs[kk][tx * TN];
            *(float4*)&b[4] = *(const float4*)&Bs[kk][tx * TN + 4];
            #pragma unroll
            for (int i = 0; i < TM; i++)
                #pragma unroll
                for (int j = 0; j < TN; j++)
                    acc[i][j] = fmaf(a[i], b[j], acc[i][j]);
        }
        __syncthreads();
    }

    // Epilogue: add bias, write to g_pre
    const int cm = by * BM + ty * TM;
    const int cn = bx * BN + tx * TN;
    float4 bias0 = *(const float4*)(bias + cn);
    float4 bias1 = *(const float4*)(bias + cn + 4);
    #pragma unroll
    for (int i = 0; i < TM; i++) {
        float4 v0, v1;
        v0.x = acc[i][0] + bias0.x;
        v0.y = acc[i][1] + bias0.y;
        v0.z = acc[i][2] + bias0.z;
        v0.w = acc[i][3] + bias0.w;
        v1.x = acc[i][4] + bias1.x;
        v1.y = acc[i][5] + bias1.y;
        v1.z = acc[i][6] + bias1.z;
        v1.w = acc[i][7] + bias1.w;
        float* crow = g_pre + (size_t)(cm + i) * N + cn;
        *(float4*)(crow)     = v0;
        *(float4*)(crow + 4) = v1;
    }
}

// ---------------------------------------------------------------------------
// K2: per-row top-k via 4-pass byte radix-select on monotone uint keys.
// One block per row; row keys cached in dynamic smem (64 KB).
// ---------------------------------------------------------------------------
__global__ __launch_bounds__(256) void topk_kernel(int dsae, int k)
{
    extern __shared__ uint32_t skeys[];   // dsae keys
    __shared__ int hist[256];
    __shared__ uint32_t s_prefix;
    __shared__ int s_krem;
    __shared__ int s_cnt_gt, s_cnt_eq, s_m;

    const int row = blockIdx.x;
    const int tid = threadIdx.x;
    const float* pre = g_pre + (size_t)row * dsae;

    // Monotone map float -> uint (larger float => larger uint)
    for (int i = tid; i < dsae; i += blockDim.x) {
        uint32_t u = __float_as_uint(pre[i]);
        u = (u & 0x80000000u) ? ~u : (u | 0x80000000u);
        skeys[i] = u;
    }
    if (tid == 0) { s_prefix = 0u; s_krem = k; }
    __syncthreads();

    for (int pass = 0; pass < 4; pass++) {
        const int shift = 24 - 8 * pass;
        const uint32_t mask_hi = (pass == 0) ? 0u : (0xFFFFFFFFu << (shift + 8));

        if (tid < 256) hist[tid] = 0;
        __syncthreads();
        const uint32_t pref = s_prefix;
        for (int i = tid; i < dsae; i += blockDim.x) {
            uint32_t u = skeys[i];
            if ((u & mask_hi) == pref)
                atomicAdd(&hist[(u >> shift) & 0xFF], 1);
        }
        __syncthreads();
        if (tid == 0) {
            int cum = 0;
            int b = 255;
            for (; b > 0; b--) {
                int c = hist[b];
                if (cum + c >= s_krem) break;
                cum += c;
            }
            s_prefix = pref | ((uint32_t)b << shift);
            s_krem -= cum;
        }
        __syncthreads();
    }

    const uint32_t T = s_prefix;  // exact key of the k-th largest value
    if (tid == 0) { s_m = k - s_krem; s_cnt_gt = 0; s_cnt_eq = 0; }
    __syncthreads();
    const int m = s_m;   // count strictly greater than T

    for (int i = tid; i < dsae; i += blockDim.x) {
        uint32_t u = skeys[i];
        int slot = -1;
        if (u > T) {
            slot = atomicAdd(&s_cnt_gt, 1);
        } else if (u == T) {
            int p = atomicAdd(&s_cnt_eq, 1);
            if (m + p < k) slot = m + p;
        }
        if (slot >= 0) {
            uint32_t ob = (u & 0x80000000u) ? (u ^ 0x80000000u) : ~u;
            float f = __uint_as_float(ob);
            g_idx[row * k + slot] = i;
            g_val[row * k + slot] = fmaxf(f, 0.0f);   // ReLU on kept activations
        }
    }
}

// ---------------------------------------------------------------------------
// K3: sparse decode  recon[row] = sum_j val_j * W_dec[idx_j, :] + b_dec
// One block per row, 512 threads, 4 columns each via float4.
// ---------------------------------------------------------------------------
__global__ __launch_bounds__(512) void decode_kernel(
    const float* __restrict__ Wdec,
    const float* __restrict__ bdec,
    float* __restrict__ out,
    int din, int k)
{
    __shared__ int   sidx[KTOP];
    __shared__ float sval[KTOP];

    const int row = blockIdx.x;
    const int tid = threadIdx.x;
    if (tid < k) {
        sidx[tid] = g_idx[row * k + tid];
        sval[tid] = g_val[row * k + tid];
    }
    __syncthreads();

    const int c = tid * 4;
    if (c < din) {
        float4 acc = *(const float4*)(bdec + c);
        #pragma unroll 8
        for (int j = 0; j < KTOP; j++) {
            float v = sval[j];
            const float4 w = *(const float4*)(Wdec + (size_t)sidx[j] * din + c);
            acc.x = fmaf(v, w.x, acc.x);
            acc.y = fmaf(v, w.y, acc.y);
            acc.z = fmaf(v, w.z, acc.z);
            acc.w = fmaf(v, w.w, acc.w);
        }
        *(float4*)(out + (size_t)row * din + c) = acc;
    }
}

// ---------------------------------------------------------------------------
// Launch
// ---------------------------------------------------------------------------
extern "C" void kernel_launch(void* const* d_in, const int* in_sizes, int n_in,
                              void* d_out, int out_size)
{
    const float* x     = (const float*)d_in[0];
    const float* W_enc = (const float*)d_in[1];
    const float* W_dec = (const float*)d_in[2];
    const float* b_enc = (const float*)d_in[3];
    const float* b_dec = (const float*)d_in[4];
    // d_in[5] is k (device int); fixed to 64 by setup_inputs.

    const int din  = in_sizes[4];          // 2048
    const int dsae = in_sizes[3];          // 16384
    const int M    = in_sizes[0] / din;    // 8192
    float* out = (float*)d_out;

    // K1: encode GEMM (+bias) -> g_pre
    dim3 grid1(dsae / BN, M / BM);
    sgemm_bias_kernel<<<grid1, 256>>>(x, W_enc, b_enc, M, dsae, din);

    // K2: top-k per row (needs 64 KB dynamic smem)
    const size_t smem = (size_t)dsae * sizeof(uint32_t);
    cudaFuncSetAttribute(topk_kernel, cudaFuncAttributeMaxDynamicSharedMemorySize,
                         (int)smem);
    topk_kernel<<<M, 256, smem>>>(dsae, KTOP);

    // K3: sparse decode -> out
    decode_kernel<<<M, 512>>>(W_dec, b_dec, out, din, KTOP);
}

// round 7
// speedup vs baseline: 3.5165x; 3.5165x over previous
#include <cuda_runtime.h>
#include <cuda_bf16.h>
#include <cstdint>

// ---------------------------------------------------------------------------
// Problem shape (fixed by setup_inputs)
// ---------------------------------------------------------------------------
#define D_IN   2048
#define D_SAE  16384
#define NROWS  8192
#define KTOP   64
#define NCAND  96

// ---------------------------------------------------------------------------
// GEMM tiling (plain bf16 mma.sync, approximate pre-acts)
// ---------------------------------------------------------------------------
#define BM 128
#define BN 128
#define BKE 32                         // K elems per stage (32 bf16 = 64 B rows)
#define NSTEPS (D_IN / BKE)            // 64
#define BUF_BYTES  (128 * 64)          // one operand buffer: 128 rows x 64 B = 8 KB
#define STAGE_BYTES (2 * BUF_BYTES)    // Ah, Bh = 16 KB
#define STAGES 4
#define GEMM_SMEM (STAGES * STAGE_BYTES)   // 64 KB

// ---------------------------------------------------------------------------
// Device-global scratch (allocation-free per harness rules)
// ---------------------------------------------------------------------------
__device__ float g_pre[(size_t)NROWS * D_SAE];         // 512 MB approx pre-acts
__device__ int   g_cidx[(size_t)NROWS * NCAND];        // candidate indices
__device__ int   g_idx[NROWS * KTOP];
__device__ float g_val[NROWS * KTOP];
__device__ __nv_bfloat16 g_xh[(size_t)NROWS * D_IN];   // x bf16
__device__ __nv_bfloat16 g_wh[(size_t)D_SAE * D_IN];   // W_enc^T bf16 [d_sae,d_in]
__device__ float g_wt[(size_t)D_SAE * D_IN];           // W_enc^T fp32 [d_sae,d_in]

// ---------------------------------------------------------------------------
// Helpers
// ---------------------------------------------------------------------------
__device__ __forceinline__ uint32_t smem_u32(const void* p) {
    return (uint32_t)__cvta_generic_to_shared(p);
}

// Swizzled byte offset inside one 8 KB operand buffer: 64 B rows, 4x 16B chunks
__device__ __forceinline__ uint32_t swz(int row, int chunk) {
    return (uint32_t)(row * 64 + ((chunk ^ ((row >> 1) & 3)) << 4));
}

__device__ __forceinline__ void cp16(uint32_t dst, const void* src) {
    asm volatile("cp.async.cg.shared.global [%0], [%1], 16;"
                 :: "r"(dst), "l"(src) : "memory");
}

__device__ __forceinline__ void ldmx4(uint32_t* r, uint32_t addr) {
    asm volatile("ldmatrix.sync.aligned.m8n8.x4.shared.b16 {%0,%1,%2,%3}, [%4];"
                 : "=r"(r[0]), "=r"(r[1]), "=r"(r[2]), "=r"(r[3]) : "r"(addr));
}

__device__ __forceinline__ void mma_bf16(float* d, const uint32_t* a, const uint32_t* b) {
    asm volatile(
        "mma.sync.aligned.m16n8k16.row.col.f32.bf16.bf16.f32 "
        "{%0,%1,%2,%3}, {%4,%5,%6,%7}, {%8,%9}, {%0,%1,%2,%3};"
        : "+f"(d[0]), "+f"(d[1]), "+f"(d[2]), "+f"(d[3])
        : "r"(a[0]), "r"(a[1]), "r"(a[2]), "r"(a[3]), "r"(b[0]), "r"(b[1]));
}

// ---------------------------------------------------------------------------
// K0a: x -> bf16
// ---------------------------------------------------------------------------
__global__ __launch_bounds__(256) void convert_x_kernel(const float* __restrict__ x) {
    size_t i = ((size_t)blockIdx.x * 256 + threadIdx.x) * 4;
    float4 v = *(const float4*)(x + i);
    __nv_bfloat16 h[4];
    h[0] = __float2bfloat16_rn(v.x);
    h[1] = __float2bfloat16_rn(v.y);
    h[2] = __float2bfloat16_rn(v.z);
    h[3] = __float2bfloat16_rn(v.w);
    *(uint2*)(g_xh + i) = *(const uint2*)h;
}

// ---------------------------------------------------------------------------
// K0b: transpose W_enc [d_in, d_sae] -> W^T fp32 + bf16 [d_sae, d_in]
// ---------------------------------------------------------------------------
__global__ __launch_bounds__(256) void convert_wt_kernel(const float* __restrict__ W) {
    __shared__ float sv[32][33];
    const int bx = blockIdx.x;          // d_sae tile
    const int by = blockIdx.y;          // d_in tile
    const int tx = threadIdx.x & 31;
    const int ty = threadIdx.x >> 5;    // 0..7

    #pragma unroll
    for (int r = ty; r < 32; r += 8)
        sv[r][tx] = W[(size_t)(by * 32 + r) * D_SAE + bx * 32 + tx];
    __syncthreads();
    #pragma unroll
    for (int r = ty; r < 32; r += 8) {
        size_t o = (size_t)(bx * 32 + r) * D_IN + by * 32 + tx;
        float v = sv[tx][r];
        g_wt[o] = v;
        g_wh[o] = __float2bfloat16_rn(v);
    }
}

// ---------------------------------------------------------------------------
// K1: bf16 mma.sync GEMM  g_pre ~= x @ W_enc + b_enc   (approximate)
// CTA 128x128, BK=32, 4-stage cp.async pipeline, 8 warps (2m x 4n), 64x32/warp
// ---------------------------------------------------------------------------
__global__ __launch_bounds__(256) void gemm_bf16_kernel(const float* __restrict__ bias)
{
    extern __shared__ __align__(128) char smem[];
    const uint32_t sb = smem_u32(smem);
    const int tid  = threadIdx.x;
    const int lane = tid & 31;
    const int wid  = tid >> 5;
    const int wm   = wid & 1;           // 2 warp rows (m)
    const int wn   = wid >> 1;          // 4 warp cols (n)

    // 8x8 supertile raster for L2 reuse: grid = 64 (m) x 128 (n) tiles
    const int g      = blockIdx.x;
    const int group  = g >> 6;          // 0..127 : 8 (m) x 16 (n) groups
    const int within = g & 63;
    const int by = (group & 7) * 8 + (within & 7);    // 0..63
    const int bx = (group >> 3) * 8 + (within >> 3);  // 0..127
    const int m0 = by * BM;
    const int n0 = bx * BN;

    // ---- stage loader: 1024 x 16B chunks (Ah, Bh) ----
    auto load_stage = [&](int stage, int kt) {
        const uint32_t base = sb + stage * STAGE_BYTES;
        const size_t kb = (size_t)kt * BKE;
        #pragma unroll
        for (int i = 0; i < 4; i++) {
            const int c     = i * 256 + tid;       // 0..1023
            const int buf   = c >> 9;              // 0=A, 1=B
            const int idx   = c & 511;
            const int row   = idx >> 2;
            const int chunk = idx & 3;
            const uint32_t dst = base + buf * BUF_BYTES + swz(row, chunk);
            const __nv_bfloat16* src = (buf == 0)
                ? g_xh + (size_t)(m0 + row) * D_IN + kb + chunk * 8
                : g_wh + (size_t)(n0 + row) * D_IN + kb + chunk * 8;
            cp16(dst, src);
        }
    };

    float acc[4][4][4];
    #pragma unroll
    for (int i = 0; i < 4; i++)
        #pragma unroll
        for (int j = 0; j < 4; j++)
            #pragma unroll
            for (int e = 0; e < 4; e++)
                acc[i][j][e] = 0.0f;

    // Prologue: fill stages 0..2
    #pragma unroll
    for (int s = 0; s < 3; s++) {
        load_stage(s, s);
        asm volatile("cp.async.commit_group;" ::: "memory");
    }

    for (int kt = 0; kt < NSTEPS; kt++) {
        asm volatile("cp.async.wait_group 2;" ::: "memory");
        __syncthreads();

        // exactly one commit per iteration (empty in the tail) keeps
        // wait_group accounting uniform
        if (kt + 3 < NSTEPS) load_stage((kt + 3) % STAGES, kt + 3);
        asm volatile("cp.async.commit_group;" ::: "memory");

        const uint32_t st = sb + (kt % STAGES) * STAGE_BYTES;

        #pragma unroll
        for (int h = 0; h < 2; h++) {     // two k16 halves of BK=32
            uint32_t ah[4][4], bh[4][2];

            #pragma unroll
            for (int im = 0; im < 4; im++) {
                const int row   = wm * 64 + im * 16 + (lane & 15);
                const int chunk = 2 * h + (lane >> 4);
                ldmx4(ah[im], st + swz(row, chunk));
            }
            #pragma unroll
            for (int p = 0; p < 2; p++) {
                const int row   = wn * 32 + p * 16 + (lane & 15);
                const int chunk = 2 * h + (lane >> 4);
                uint32_t r[4];
                ldmx4(r, st + BUF_BYTES + swz(row, chunk));
                bh[2*p][0]   = r[0]; bh[2*p][1]   = r[2];
                bh[2*p+1][0] = r[1]; bh[2*p+1][1] = r[3];
            }

            #pragma unroll
            for (int im = 0; im < 4; im++)
                #pragma unroll
                for (int in = 0; in < 4; in++)
                    mma_bf16(acc[im][in], ah[im], bh[in]);
        }
    }

    // Epilogue: registers -> g_pre (+bias)
    #pragma unroll
    for (int im = 0; im < 4; im++) {
        #pragma unroll
        for (int in = 0; in < 4; in++) {
            const int mr = m0 + wm * 64 + im * 16 + (lane >> 2);
            const int nc = n0 + wn * 32 + in * 8 + (lane & 3) * 2;
            const float2 bv = *(const float2*)(bias + nc);
            float2 v0 = { acc[im][in][0] + bv.x, acc[im][in][1] + bv.y };
            float2 v1 = { acc[im][in][2] + bv.x, acc[im][in][3] + bv.y };
            *(float2*)(g_pre + (size_t)mr * D_SAE + nc)       = v0;
            *(float2*)(g_pre + (size_t)(mr + 8) * D_SAE + nc) = v1;
        }
    }
}

// ---------------------------------------------------------------------------
// K2: per-row top-NCAND candidate indices via 4-pass byte radix-select
// ---------------------------------------------------------------------------
__global__ __launch_bounds__(256) void topk_kernel(int dsae, int k)
{
    extern __shared__ uint32_t skeys[];
    __shared__ int hist[256];
    __shared__ uint32_t s_prefix;
    __shared__ int s_krem;
    __shared__ int s_cnt_gt, s_cnt_eq, s_m;

    const int row = blockIdx.x;
    const int tid = threadIdx.x;
    const float* pre = g_pre + (size_t)row * dsae;

    for (int i = tid; i < dsae; i += blockDim.x) {
        uint32_t u = __float_as_uint(pre[i]);
        u = (u & 0x80000000u) ? ~u : (u | 0x80000000u);
        skeys[i] = u;
    }
    if (tid == 0) { s_prefix = 0u; s_krem = k; }
    __syncthreads();

    for (int pass = 0; pass < 4; pass++) {
        const int shift = 24 - 8 * pass;
        const uint32_t mask_hi = (pass == 0) ? 0u : (0xFFFFFFFFu << (shift + 8));

        if (tid < 256) hist[tid] = 0;
        __syncthreads();
        const uint32_t pref = s_prefix;
        for (int i = tid; i < dsae; i += blockDim.x) {
            uint32_t u = skeys[i];
            if ((u & mask_hi) == pref)
                atomicAdd(&hist[(u >> shift) & 0xFF], 1);
        }
        __syncthreads();
        if (tid == 0) {
            int cum = 0;
            int b = 255;
            for (; b > 0; b--) {
                int c = hist[b];
                if (cum + c >= s_krem) break;
                cum += c;
            }
            s_prefix = pref | ((uint32_t)b << shift);
            s_krem -= cum;
        }
        __syncthreads();
    }

    const uint32_t T = s_prefix;
    if (tid == 0) { s_m = k - s_krem; s_cnt_gt = 0; s_cnt_eq = 0; }
    __syncthreads();
    const int m = s_m;

    for (int i = tid; i < dsae; i += blockDim.x) {
        uint32_t u = skeys[i];
        int slot = -1;
        if (u > T) {
            slot = atomicAdd(&s_cnt_gt, 1);
        } else if (u == T) {
            int p = atomicAdd(&s_cnt_eq, 1);
            if (m + p < k) slot = m + p;
        }
        if (slot >= 0)
            g_cidx[(size_t)row * k + slot] = i;
    }
}

// ---------------------------------------------------------------------------
// K2b: exact fp32 rescore of NCAND candidates + exact top-64 selection.
// One block per row, 256 threads (8 warps). x row cached in smem; each warp
// computes fp32 dots against g_wt candidate rows (coalesced, ~L2-resident).
// ---------------------------------------------------------------------------
__global__ __launch_bounds__(256) void rescore_kernel(
    const float* __restrict__ x,
    const float* __restrict__ b_enc)
{
    __shared__ float sx[D_IN];
    __shared__ float scval[NCAND];
    __shared__ int   scidx[NCAND];

    const int row  = blockIdx.x;
    const int tid  = threadIdx.x;
    const int lane = tid & 31;
    const int wid  = tid >> 5;

    if (tid < NCAND) scidx[tid] = g_cidx[(size_t)row * NCAND + tid];
    {
        const float4* xr = (const float4*)(x + (size_t)row * D_IN);
        #pragma unroll
        for (int i = 0; i < D_IN / 4 / 256; i++) {
            const int j = i * 256 + tid;
            *(float4*)(sx + j * 4) = xr[j];
        }
    }
    __syncthreads();

    // each warp handles NCAND/8 = 12 candidates
    for (int c = wid; c < NCAND; c += 8) {
        const float* w = g_wt + (size_t)scidx[c] * D_IN;
        float s = 0.0f;
        #pragma unroll
        for (int j0 = 0; j0 < D_IN; j0 += 128) {
            const int j = j0 + lane * 4;
            float4 wv = *(const float4*)(w + j);
            float4 xv = *(const float4*)(sx + j);
            s = fmaf(wv.x, xv.x, s);
            s = fmaf(wv.y, xv.y, s);
            s = fmaf(wv.z, xv.z, s);
            s = fmaf(wv.w, xv.w, s);
        }
        #pragma unroll
        for (int o = 16; o > 0; o >>= 1)
            s += __shfl_xor_sync(0xFFFFFFFFu, s, o);
        if (lane == 0) scval[c] = s + __ldg(b_enc + scidx[c]);
    }
    __syncthreads();

    // exact rank among NCAND (ties: lower index wins, matching jax top_k)
    if (tid < NCAND) {
        const float v = scval[tid];
        const int   ix = scidx[tid];
        int rank = 0;
        #pragma unroll 8
        for (int o = 0; o < NCAND; o++) {
            float ov = scval[o];
            rank += (ov > v) || (ov == v && scidx[o] < ix);
        }
        if (rank < KTOP) {
            g_idx[row * KTOP + rank] = ix;
            g_val[row * KTOP + rank] = fmaxf(v, 0.0f);
        }
    }
}

// ---------------------------------------------------------------------------
// K3: sparse decode (unchanged, verified in R3)
// ---------------------------------------------------------------------------
__global__ __launch_bounds__(512) void decode_kernel(
    const float* __restrict__ Wdec,
    const float* __restrict__ bdec,
    float* __restrict__ out,
    int din, int k)
{
    __shared__ int   sidx[KTOP];
    __shared__ float sval[KTOP];

    const int row = blockIdx.x;
    const int tid = threadIdx.x;
    if (tid < k) {
        sidx[tid] = g_idx[row * k + tid];
        sval[tid] = g_val[row * k + tid];
    }
    __syncthreads();

    const int c = tid * 4;
    if (c < din) {
        float4 acc = *(const float4*)(bdec + c);
        #pragma unroll 8
        for (int j = 0; j < KTOP; j++) {
            float v = sval[j];
            const float4 w = *(const float4*)(Wdec + (size_t)sidx[j] * din + c);
            acc.x = fmaf(v, w.x, acc.x);
            acc.y = fmaf(v, w.y, acc.y);
            acc.z = fmaf(v, w.z, acc.z);
            acc.w = fmaf(v, w.w, acc.w);
        }
        *(float4*)(out + (size_t)row * din + c) = acc;
    }
}

// ---------------------------------------------------------------------------
// Host launch
// ---------------------------------------------------------------------------
extern "C" void kernel_launch(void* const* d_in, const int* in_sizes, int n_in,
                              void* d_out, int out_size)
{
    const float* x     = (const float*)d_in[0];
    const float* W_enc = (const float*)d_in[1];
    const float* W_dec = (const float*)d_in[2];
    const float* b_enc = (const float*)d_in[3];
    const float* b_dec = (const float*)d_in[4];

    const int din  = in_sizes[4];          // 2048
    const int dsae = in_sizes[3];          // 16384
    const int M    = in_sizes[0] / din;    // 8192
    float* out = (float*)d_out;

    // K0: conversions (+ W transpose, fp32 and bf16)
    convert_x_kernel<<<(NROWS * D_IN) / 1024, 256>>>(x);
    dim3 gw(D_SAE / 32, D_IN / 32);
    convert_wt_kernel<<<gw, 256>>>(W_enc);

    // K1: approximate bf16 GEMM
    cudaFuncSetAttribute(gemm_bf16_kernel,
                         cudaFuncAttributeMaxDynamicSharedMemorySize, GEMM_SMEM);
    const int n_tiles = (M / BM) * (dsae / BN);   // 8192
    gemm_bf16_kernel<<<n_tiles, 256, GEMM_SMEM>>>(b_enc);

    // K2: top-NCAND candidate indices per row
    const size_t smem = (size_t)dsae * sizeof(uint32_t);
    cudaFuncSetAttribute(topk_kernel, cudaFuncAttributeMaxDynamicSharedMemorySize,
                         (int)smem);
    topk_kernel<<<M, 256, smem>>>(dsae, NCAND);

    // K2b: exact rescore + exact top-64
    rescore_kernel<<<M, 256>>>(x, b_enc);

    // K3: sparse decode
    decode_kernel<<<M, 512>>>(W_dec, b_dec, out, din, KTOP);
}

// round 8
// speedup vs baseline: 4.7821x; 1.3599x over previous
#include <cuda_runtime.h>
#include <cuda_bf16.h>
#include <cstdint>

// ---------------------------------------------------------------------------
// Problem shape (fixed by setup_inputs)
// ---------------------------------------------------------------------------
#define D_IN   2048
#define D_SAE  16384
#define NROWS  8192
#define KTOP   64
#define NCAND  96

// ---------------------------------------------------------------------------
// GEMM tiling (plain bf16 mma.sync, approximate pre-acts -> u16 keys)
// ---------------------------------------------------------------------------
#define BM 128
#define BN 128
#define BKE 32                         // K elems per stage (32 bf16 = 64 B rows)
#define NSTEPS (D_IN / BKE)            // 64
#define BUF_BYTES  (128 * 64)          // one operand buffer: 128 rows x 64 B = 8 KB
#define STAGE_BYTES (2 * BUF_BYTES)    // Ah, Bh = 16 KB
#define STAGES 4
#define GEMM_SMEM (STAGES * STAGE_BYTES)   // 64 KB

// ---------------------------------------------------------------------------
// Device-global scratch (allocation-free per harness rules)
// ---------------------------------------------------------------------------
__device__ uint16_t g_key[(size_t)NROWS * D_SAE];      // 256 MB approx-rank keys
__device__ int   g_cidx[(size_t)NROWS * NCAND];        // candidate indices
__device__ int   g_idx[NROWS * KTOP];
__device__ float g_val[NROWS * KTOP];
__device__ __nv_bfloat16 g_xh[(size_t)NROWS * D_IN];   // x bf16
__device__ __nv_bfloat16 g_wh[(size_t)D_SAE * D_IN];   // W_enc^T bf16 [d_sae,d_in]
__device__ float g_wt[(size_t)D_SAE * D_IN];           // W_enc^T fp32 [d_sae,d_in]

// ---------------------------------------------------------------------------
// Helpers
// ---------------------------------------------------------------------------
__device__ __forceinline__ uint32_t smem_u32(const void* p) {
    return (uint32_t)__cvta_generic_to_shared(p);
}

// Swizzled byte offset inside one 8 KB operand buffer: 64 B rows, 4x 16B chunks
__device__ __forceinline__ uint32_t swz(int row, int chunk) {
    return (uint32_t)(row * 64 + ((chunk ^ ((row >> 1) & 3)) << 4));
}

__device__ __forceinline__ void cp16(uint32_t dst, const void* src) {
    asm volatile("cp.async.cg.shared.global [%0], [%1], 16;"
                 :: "r"(dst), "l"(src) : "memory");
}

__device__ __forceinline__ void ldmx4(uint32_t* r, uint32_t addr) {
    asm volatile("ldmatrix.sync.aligned.m8n8.x4.shared.b16 {%0,%1,%2,%3}, [%4];"
                 : "=r"(r[0]), "=r"(r[1]), "=r"(r[2]), "=r"(r[3]) : "r"(addr));
}

__device__ __forceinline__ void mma_bf16(float* d, const uint32_t* a, const uint32_t* b) {
    asm volatile(
        "mma.sync.aligned.m16n8k16.row.col.f32.bf16.bf16.f32 "
        "{%0,%1,%2,%3}, {%4,%5,%6,%7}, {%8,%9}, {%0,%1,%2,%3};"
        : "+f"(d[0]), "+f"(d[1]), "+f"(d[2]), "+f"(d[3])
        : "r"(a[0]), "r"(a[1]), "r"(a[2]), "r"(a[3]), "r"(b[0]), "r"(b[1]));
}

// Monotone u16 key: larger float => larger key (bf16-quantized)
__device__ __forceinline__ uint16_t fkey(float v) {
    uint16_t b = __bfloat16_as_ushort(__float2bfloat16_rn(v));
    return (b & 0x8000) ? (uint16_t)~b : (uint16_t)(b | 0x8000u);
}

// ---------------------------------------------------------------------------
// K0a: x -> bf16
// ---------------------------------------------------------------------------
__global__ __launch_bounds__(256) void convert_x_kernel(const float* __restrict__ x) {
    size_t i = ((size_t)blockIdx.x * 256 + threadIdx.x) * 4;
    float4 v = *(const float4*)(x + i);
    __nv_bfloat16 h[4];
    h[0] = __float2bfloat16_rn(v.x);
    h[1] = __float2bfloat16_rn(v.y);
    h[2] = __float2bfloat16_rn(v.z);
    h[3] = __float2bfloat16_rn(v.w);
    *(uint2*)(g_xh + i) = *(const uint2*)h;
}

// ---------------------------------------------------------------------------
// K0b: transpose W_enc [d_in, d_sae] -> W^T fp32 + bf16 [d_sae, d_in]
// ---------------------------------------------------------------------------
__global__ __launch_bounds__(256) void convert_wt_kernel(const float* __restrict__ W) {
    __shared__ float sv[32][33];
    const int bx = blockIdx.x;          // d_sae tile
    const int by = blockIdx.y;          // d_in tile
    const int tx = threadIdx.x & 31;
    const int ty = threadIdx.x >> 5;    // 0..7

    #pragma unroll
    for (int r = ty; r < 32; r += 8)
        sv[r][tx] = W[(size_t)(by * 32 + r) * D_SAE + bx * 32 + tx];
    __syncthreads();
    #pragma unroll
    for (int r = ty; r < 32; r += 8) {
        size_t o = (size_t)(bx * 32 + r) * D_IN + by * 32 + tx;
        float v = sv[tx][r];
        g_wt[o] = v;
        g_wh[o] = __float2bfloat16_rn(v);
    }
}

// ---------------------------------------------------------------------------
// K1: bf16 mma.sync GEMM -> u16 ranking keys  (approximate pre-acts)
// CTA 128x128, BK=32, 4-stage cp.async pipeline, 8 warps (2m x 4n), 64x32/warp
// ---------------------------------------------------------------------------
__global__ __launch_bounds__(256) void gemm_bf16_kernel(const float* __restrict__ bias)
{
    extern __shared__ __align__(128) char smem[];
    const uint32_t sb = smem_u32(smem);
    const int tid  = threadIdx.x;
    const int lane = tid & 31;
    const int wid  = tid >> 5;
    const int wm   = wid & 1;           // 2 warp rows (m)
    const int wn   = wid >> 1;          // 4 warp cols (n)

    // 8x8 supertile raster for L2 reuse: grid = 64 (m) x 128 (n) tiles
    const int g      = blockIdx.x;
    const int group  = g >> 6;          // 0..127 : 8 (m) x 16 (n) groups
    const int within = g & 63;
    const int by = (group & 7) * 8 + (within & 7);    // 0..63
    const int bx = (group >> 3) * 8 + (within >> 3);  // 0..127
    const int m0 = by * BM;
    const int n0 = bx * BN;

    // ---- stage loader: 1024 x 16B chunks (Ah, Bh) ----
    auto load_stage = [&](int stage, int kt) {
        const uint32_t base = sb + stage * STAGE_BYTES;
        const size_t kb = (size_t)kt * BKE;
        #pragma unroll
        for (int i = 0; i < 4; i++) {
            const int c     = i * 256 + tid;       // 0..1023
            const int buf   = c >> 9;              // 0=A, 1=B
            const int idx   = c & 511;
            const int row   = idx >> 2;
            const int chunk = idx & 3;
            const uint32_t dst = base + buf * BUF_BYTES + swz(row, chunk);
            const __nv_bfloat16* src = (buf == 0)
                ? g_xh + (size_t)(m0 + row) * D_IN + kb + chunk * 8
                : g_wh + (size_t)(n0 + row) * D_IN + kb + chunk * 8;
            cp16(dst, src);
        }
    };

    float acc[4][4][4];
    #pragma unroll
    for (int i = 0; i < 4; i++)
        #pragma unroll
        for (int j = 0; j < 4; j++)
            #pragma unroll
            for (int e = 0; e < 4; e++)
                acc[i][j][e] = 0.0f;

    // Prologue: fill stages 0..2
    #pragma unroll
    for (int s = 0; s < 3; s++) {
        load_stage(s, s);
        asm volatile("cp.async.commit_group;" ::: "memory");
    }

    for (int kt = 0; kt < NSTEPS; kt++) {
        asm volatile("cp.async.wait_group 2;" ::: "memory");
        __syncthreads();

        // exactly one commit per iteration (empty in the tail)
        if (kt + 3 < NSTEPS) load_stage((kt + 3) % STAGES, kt + 3);
        asm volatile("cp.async.commit_group;" ::: "memory");

        const uint32_t st = sb + (kt % STAGES) * STAGE_BYTES;

        #pragma unroll
        for (int h = 0; h < 2; h++) {     // two k16 halves of BK=32
            uint32_t ah[4][4], bh[4][2];

            #pragma unroll
            for (int im = 0; im < 4; im++) {
                const int row   = wm * 64 + im * 16 + (lane & 15);
                const int chunk = 2 * h + (lane >> 4);
                ldmx4(ah[im], st + swz(row, chunk));
            }
            #pragma unroll
            for (int p = 0; p < 2; p++) {
                const int row   = wn * 32 + p * 16 + (lane & 15);
                const int chunk = 2 * h + (lane >> 4);
                uint32_t r[4];
                ldmx4(r, st + BUF_BYTES + swz(row, chunk));
                bh[2*p][0]   = r[0]; bh[2*p][1]   = r[2];
                bh[2*p+1][0] = r[1]; bh[2*p+1][1] = r[3];
            }

            #pragma unroll
            for (int im = 0; im < 4; im++)
                #pragma unroll
                for (int in = 0; in < 4; in++)
                    mma_bf16(acc[im][in], ah[im], bh[in]);
        }
    }

    // Epilogue: registers -> u16 ranking keys (+bias), one u32 store per pair
    #pragma unroll
    for (int im = 0; im < 4; im++) {
        #pragma unroll
        for (int in = 0; in < 4; in++) {
            const int mr = m0 + wm * 64 + im * 16 + (lane >> 2);
            const int nc = n0 + wn * 32 + in * 8 + (lane & 3) * 2;
            const float2 bv = *(const float2*)(bias + nc);
            const uint32_t k0 = (uint32_t)fkey(acc[im][in][0] + bv.x)
                              | ((uint32_t)fkey(acc[im][in][1] + bv.y) << 16);
            const uint32_t k1 = (uint32_t)fkey(acc[im][in][2] + bv.x)
                              | ((uint32_t)fkey(acc[im][in][3] + bv.y) << 16);
            *(uint32_t*)(g_key + (size_t)mr * D_SAE + nc)       = k0;
            *(uint32_t*)(g_key + (size_t)(mr + 8) * D_SAE + nc) = k1;
        }
    }
}

// ---------------------------------------------------------------------------
// K2: per-row top-NCAND candidate indices via 2-pass byte radix-select on u16
// keys. 32 KB smem/row -> ~7 blocks/SM.
// ---------------------------------------------------------------------------
__global__ __launch_bounds__(256) void topk16_kernel(int k)
{
    __shared__ __align__(16) uint16_t skeys[D_SAE];    // 32 KB
    __shared__ int hist[256];
    __shared__ uint32_t s_prefix;
    __shared__ int s_krem;
    __shared__ int s_cnt_gt, s_cnt_eq, s_m;

    const int row = blockIdx.x;
    const int tid = threadIdx.x;
    const uint4* src = (const uint4*)(g_key + (size_t)row * D_SAE);

    // load 16384 u16 = 2048 uint4
    #pragma unroll
    for (int i = 0; i < D_SAE / 8 / 256; i++) {        // 8 iters
        const int j = i * 256 + tid;
        *(uint4*)(skeys + j * 8) = src[j];
    }
    if (tid == 0) { s_prefix = 0u; s_krem = k; }
    hist[tid] = 0;
    __syncthreads();

    // ---- pass 0: high byte ----
    for (int i = tid; i < D_SAE; i += 256)
        atomicAdd(&hist[skeys[i] >> 8], 1);
    __syncthreads();
    if (tid == 0) {
        int cum = 0, b = 255;
        for (; b > 0; b--) {
            int c = hist[b];
            if (cum + c >= s_krem) break;
            cum += c;
        }
        s_prefix = (uint32_t)b << 8;
        s_krem -= cum;
    }
    __syncthreads();
    const uint32_t hi = s_prefix;
    hist[tid] = 0;
    __syncthreads();

    // ---- pass 1: low byte among keys with matching high byte ----
    for (int i = tid; i < D_SAE; i += 256) {
        uint32_t u = skeys[i];
        if ((u & 0xFF00u) == hi)
            atomicAdd(&hist[u & 0xFFu], 1);
    }
    __syncthreads();
    if (tid == 0) {
        int cum = 0, b = 255;
        for (; b > 0; b--) {
            int c = hist[b];
            if (cum + c >= s_krem) break;
            cum += c;
        }
        s_prefix = hi | (uint32_t)b;
        s_krem -= cum;
        s_m = k - s_krem;
        s_cnt_gt = 0;
        s_cnt_eq = 0;
    }
    __syncthreads();

    const uint32_t T = s_prefix;   // key of the k-th largest (with ties)
    const int m = s_m;             // count strictly greater than T

    for (int i = tid; i < D_SAE; i += 256) {
        uint32_t u = skeys[i];
        int slot = -1;
        if (u > T) {
            slot = atomicAdd(&s_cnt_gt, 1);
        } else if (u == T) {
            int p = atomicAdd(&s_cnt_eq, 1);
            if (m + p < k) slot = m + p;
        }
        if (slot >= 0)
            g_cidx[(size_t)row * k + slot] = i;
    }
}

// ---------------------------------------------------------------------------
// K2b: exact fp32 rescore of NCAND candidates + exact top-64 selection.
// One block per row, 256 threads (8 warps). x row cached in smem; each warp
// computes fp32 dots against g_wt candidate rows (coalesced, ~L2-resident).
// ---------------------------------------------------------------------------
__global__ __launch_bounds__(256) void rescore_kernel(
    const float* __restrict__ x,
    const float* __restrict__ b_enc)
{
    __shared__ float sx[D_IN];
    __shared__ float scval[NCAND];
    __shared__ int   scidx[NCAND];

    const int row  = blockIdx.x;
    const int tid  = threadIdx.x;
    const int lane = tid & 31;
    const int wid  = tid >> 5;

    if (tid < NCAND) scidx[tid] = g_cidx[(size_t)row * NCAND + tid];
    {
        const float4* xr = (const float4*)(x + (size_t)row * D_IN);
        #pragma unroll
        for (int i = 0; i < D_IN / 4 / 256; i++) {
            const int j = i * 256 + tid;
            *(float4*)(sx + j * 4) = xr[j];
        }
    }
    __syncthreads();

    // each warp handles NCAND/8 = 12 candidates
    for (int c = wid; c < NCAND; c += 8) {
        const float* w = g_wt + (size_t)scidx[c] * D_IN;
        float s = 0.0f;
        #pragma unroll
        for (int j0 = 0; j0 < D_IN; j0 += 128) {
            const int j = j0 + lane * 4;
            float4 wv = *(const float4*)(w + j);
            float4 xv = *(const float4*)(sx + j);
            s = fmaf(wv.x, xv.x, s);
            s = fmaf(wv.y, xv.y, s);
            s = fmaf(wv.z, xv.z, s);
            s = fmaf(wv.w, xv.w, s);
        }
        #pragma unroll
        for (int o = 16; o > 0; o >>= 1)
            s += __shfl_xor_sync(0xFFFFFFFFu, s, o);
        if (lane == 0) scval[c] = s + __ldg(b_enc + scidx[c]);
    }
    __syncthreads();

    // exact rank among NCAND (ties: lower index wins, matching jax top_k)
    if (tid < NCAND) {
        const float v = scval[tid];
        const int   ix = scidx[tid];
        int rank = 0;
        #pragma unroll 8
        for (int o = 0; o < NCAND; o++) {
            float ov = scval[o];
            rank += (ov > v) || (ov == v && scidx[o] < ix);
        }
        if (rank < KTOP) {
            g_idx[row * KTOP + rank] = ix;
            g_val[row * KTOP + rank] = fmaxf(v, 0.0f);
        }
    }
}

// ---------------------------------------------------------------------------
// K3: sparse decode (unchanged, verified)
// ---------------------------------------------------------------------------
__global__ __launch_bounds__(512) void decode_kernel(
    const float* __restrict__ Wdec,
    const float* __restrict__ bdec,
    float* __restrict__ out,
    int din, int k)
{
    __shared__ int   sidx[KTOP];
    __shared__ float sval[KTOP];

    const int row = blockIdx.x;
    const int tid = threadIdx.x;
    if (tid < k) {
        sidx[tid] = g_idx[row * k + tid];
        sval[tid] = g_val[row * k + tid];
    }
    __syncthreads();

    const int c = tid * 4;
    if (c < din) {
        float4 acc = *(const float4*)(bdec + c);
        #pragma unroll 8
        for (int j = 0; j < KTOP; j++) {
            float v = sval[j];
            const float4 w = *(const float4*)(Wdec + (size_t)sidx[j] * din + c);
            acc.x = fmaf(v, w.x, acc.x);
            acc.y = fmaf(v, w.y, acc.y);
            acc.z = fmaf(v, w.z, acc.z);
            acc.w = fmaf(v, w.w, acc.w);
        }
        *(float4*)(out + (size_t)row * din + c) = acc;
    }
}

// ---------------------------------------------------------------------------
// Host launch
// ---------------------------------------------------------------------------
extern "C" void kernel_launch(void* const* d_in, const int* in_sizes, int n_in,
                              void* d_out, int out_size)
{
    const float* x     = (const float*)d_in[0];
    const float* W_enc = (const float*)d_in[1];
    const float* W_dec = (const float*)d_in[2];
    const float* b_enc = (const float*)d_in[3];
    const float* b_dec = (const float*)d_in[4];

    const int din  = in_sizes[4];          // 2048
    const int dsae = in_sizes[3];          // 16384
    const int M    = in_sizes[0] / din;    // 8192
    float* out = (float*)d_out;

    // K0: conversions (+ W transpose, fp32 and bf16)
    convert_x_kernel<<<(NROWS * D_IN) / 1024, 256>>>(x);
    dim3 gw(D_SAE / 32, D_IN / 32);
    convert_wt_kernel<<<gw, 256>>>(W_enc);

    // K1: approximate bf16 GEMM -> u16 keys
    cudaFuncSetAttribute(gemm_bf16_kernel,
                         cudaFuncAttributeMaxDynamicSharedMemorySize, GEMM_SMEM);
    const int n_tiles = (M / BM) * (dsae / BN);   // 8192
    gemm_bf16_kernel<<<n_tiles, 256, GEMM_SMEM>>>(b_enc);

    // K2: top-NCAND candidate indices per row (2-pass u16 radix-select)
    topk16_kernel<<<M, 256>>>(NCAND);

    // K2b: exact rescore + exact top-64
    rescore_kernel<<<M, 256>>>(x, b_enc);

    // K3: sparse decode
    decode_kernel<<<M, 512>>>(W_dec, b_dec, out, din, KTOP);
}

// round 9
// speedup vs baseline: 4.9555x; 1.0363x over previous
#include <cuda_runtime.h>
#include <cuda_bf16.h>
#include <cstdint>

// ---------------------------------------------------------------------------
// Problem shape (fixed by setup_inputs)
// ---------------------------------------------------------------------------
#define D_IN   2048
#define D_SAE  16384
#define NROWS  8192
#define KTOP   64
#define NCAND  96

// ---------------------------------------------------------------------------
// GEMM tiling (plain bf16 mma.sync, approximate pre-acts -> u16 keys)
// 128x128 CTA tile, 4 warps (2x2), 64x64 per warp, BK=32, 4-stage cp.async
// ---------------------------------------------------------------------------
#define BM 128
#define BN 128
#define BKE 32                         // K elems per stage (32 bf16 = 64 B rows)
#define NSTEPS (D_IN / BKE)            // 64
#define BUF_BYTES  (128 * 64)          // one operand buffer: 128 rows x 64 B = 8 KB
#define STAGE_BYTES (2 * BUF_BYTES)    // Ah, Bh = 16 KB
#define STAGES 4
#define GEMM_SMEM (STAGES * STAGE_BYTES)   // 64 KB

// ---------------------------------------------------------------------------
// Device-global scratch (allocation-free per harness rules)
// ---------------------------------------------------------------------------
__device__ uint16_t g_key[(size_t)NROWS * D_SAE];      // 256 MB approx-rank keys
__device__ int   g_cidx[(size_t)NROWS * NCAND];        // candidate indices
__device__ int   g_idx[NROWS * KTOP];
__device__ float g_val[NROWS * KTOP];
__device__ __nv_bfloat16 g_xh[(size_t)NROWS * D_IN];   // x bf16
__device__ __nv_bfloat16 g_wh[(size_t)D_SAE * D_IN];   // W_enc^T bf16 [d_sae,d_in]
__device__ float g_wt[(size_t)D_SAE * D_IN];           // W_enc^T fp32 [d_sae,d_in]

// ---------------------------------------------------------------------------
// Helpers
// ---------------------------------------------------------------------------
__device__ __forceinline__ uint32_t smem_u32(const void* p) {
    return (uint32_t)__cvta_generic_to_shared(p);
}

// Swizzled byte offset inside one 8 KB operand buffer: 64 B rows, 4x 16B chunks
__device__ __forceinline__ uint32_t swz(int row, int chunk) {
    return (uint32_t)(row * 64 + ((chunk ^ ((row >> 1) & 3)) << 4));
}

__device__ __forceinline__ void cp16(uint32_t dst, const void* src) {
    asm volatile("cp.async.cg.shared.global [%0], [%1], 16;"
                 :: "r"(dst), "l"(src) : "memory");
}

__device__ __forceinline__ void ldmx4(uint32_t* r, uint32_t addr) {
    asm volatile("ldmatrix.sync.aligned.m8n8.x4.shared.b16 {%0,%1,%2,%3}, [%4];"
                 : "=r"(r[0]), "=r"(r[1]), "=r"(r[2]), "=r"(r[3]) : "r"(addr));
}

__device__ __forceinline__ void mma_bf16(float* d, const uint32_t* a, const uint32_t* b) {
    asm volatile(
        "mma.sync.aligned.m16n8k16.row.col.f32.bf16.bf16.f32 "
        "{%0,%1,%2,%3}, {%4,%5,%6,%7}, {%8,%9}, {%0,%1,%2,%3};"
        : "+f"(d[0]), "+f"(d[1]), "+f"(d[2]), "+f"(d[3])
        : "r"(a[0]), "r"(a[1]), "r"(a[2]), "r"(a[3]), "r"(b[0]), "r"(b[1]));
}

// Monotone u16 key: larger float => larger key (bf16-quantized)
__device__ __forceinline__ uint16_t fkey(float v) {
    uint16_t b = __bfloat16_as_ushort(__float2bfloat16_rn(v));
    return (b & 0x8000) ? (uint16_t)~b : (uint16_t)(b | 0x8000u);
}

// ---------------------------------------------------------------------------
// K0a: x -> bf16
// ---------------------------------------------------------------------------
__global__ __launch_bounds__(256) void convert_x_kernel(const float* __restrict__ x) {
    size_t i = ((size_t)blockIdx.x * 256 + threadIdx.x) * 4;
    float4 v = *(const float4*)(x + i);
    __nv_bfloat16 h[4];
    h[0] = __float2bfloat16_rn(v.x);
    h[1] = __float2bfloat16_rn(v.y);
    h[2] = __float2bfloat16_rn(v.z);
    h[3] = __float2bfloat16_rn(v.w);
    *(uint2*)(g_xh + i) = *(const uint2*)h;
}

// ---------------------------------------------------------------------------
// K0b: transpose W_enc [d_in, d_sae] -> W^T fp32 + bf16 [d_sae, d_in]
// ---------------------------------------------------------------------------
__global__ __launch_bounds__(256) void convert_wt_kernel(const float* __restrict__ W) {
    __shared__ float sv[32][33];
    const int bx = blockIdx.x;          // d_sae tile
    const int by = blockIdx.y;          // d_in tile
    const int tx = threadIdx.x & 31;
    const int ty = threadIdx.x >> 5;    // 0..7

    #pragma unroll
    for (int r = ty; r < 32; r += 8)
        sv[r][tx] = W[(size_t)(by * 32 + r) * D_SAE + bx * 32 + tx];
    __syncthreads();
    #pragma unroll
    for (int r = ty; r < 32; r += 8) {
        size_t o = (size_t)(bx * 32 + r) * D_IN + by * 32 + tx;
        float v = sv[tx][r];
        g_wt[o] = v;
        g_wh[o] = __float2bfloat16_rn(v);
    }
}

// ---------------------------------------------------------------------------
// K1: bf16 mma.sync GEMM -> u16 ranking keys  (approximate pre-acts)
// 4 warps, 64x64 warp tiles: mma:ldsm ratio 4:1 -> tensor-bound
// ---------------------------------------------------------------------------
__global__ __launch_bounds__(128) void gemm_bf16_kernel(const float* __restrict__ bias)
{
    extern __shared__ __align__(128) char smem[];
    const uint32_t sb = smem_u32(smem);
    const int tid  = threadIdx.x;
    const int lane = tid & 31;
    const int wid  = tid >> 5;
    const int wm   = wid & 1;           // 2 warp rows (m)
    const int wn   = wid >> 1;          // 2 warp cols (n)

    // 8x8 supertile raster for L2 reuse: grid = 64 (m) x 128 (n) tiles
    const int g      = blockIdx.x;
    const int group  = g >> 6;          // 0..127 : 8 (m) x 16 (n) groups
    const int within = g & 63;
    const int by = (group & 7) * 8 + (within & 7);    // 0..63
    const int bx = (group >> 3) * 8 + (within >> 3);  // 0..127
    const int m0 = by * BM;
    const int n0 = bx * BN;

    // ---- stage loader: 1024 x 16B chunks (Ah, Bh), 128 threads -> 8 iters ----
    auto load_stage = [&](int stage, int kt) {
        const uint32_t base = sb + stage * STAGE_BYTES;
        const size_t kb = (size_t)kt * BKE;
        #pragma unroll
        for (int i = 0; i < 8; i++) {
            const int c     = i * 128 + tid;       // 0..1023
            const int buf   = c >> 9;              // 0=A, 1=B
            const int idx   = c & 511;
            const int row   = idx >> 2;
            const int chunk = idx & 3;
            const uint32_t dst = base + buf * BUF_BYTES + swz(row, chunk);
            const __nv_bfloat16* src = (buf == 0)
                ? g_xh + (size_t)(m0 + row) * D_IN + kb + chunk * 8
                : g_wh + (size_t)(n0 + row) * D_IN + kb + chunk * 8;
            cp16(dst, src);
        }
    };

    float acc[4][8][4];
    #pragma unroll
    for (int i = 0; i < 4; i++)
        #pragma unroll
        for (int j = 0; j < 8; j++)
            #pragma unroll
            for (int e = 0; e < 4; e++)
                acc[i][j][e] = 0.0f;

    // Prologue: fill stages 0..2
    #pragma unroll
    for (int s = 0; s < 3; s++) {
        load_stage(s, s);
        asm volatile("cp.async.commit_group;" ::: "memory");
    }

    for (int kt = 0; kt < NSTEPS; kt++) {
        asm volatile("cp.async.wait_group 2;" ::: "memory");
        __syncthreads();

        // exactly one commit per iteration (empty in the tail)
        if (kt + 3 < NSTEPS) load_stage((kt + 3) % STAGES, kt + 3);
        asm volatile("cp.async.commit_group;" ::: "memory");

        const uint32_t st = sb + (kt % STAGES) * STAGE_BYTES;

        #pragma unroll
        for (int h = 0; h < 2; h++) {     // two k16 halves of BK=32
            uint32_t ah[4][4], bh[8][2];
            const int chunk = 2 * h + (lane >> 4);

            #pragma unroll
            for (int im = 0; im < 4; im++) {
                const int row = wm * 64 + im * 16 + (lane & 15);
                ldmx4(ah[im], st + swz(row, chunk));
            }
            #pragma unroll
            for (int p = 0; p < 4; p++) {
                const int row = wn * 64 + p * 16 + (lane & 15);
                uint32_t r[4];
                ldmx4(r, st + BUF_BYTES + swz(row, chunk));
                bh[2*p][0]   = r[0]; bh[2*p][1]   = r[2];
                bh[2*p+1][0] = r[1]; bh[2*p+1][1] = r[3];
            }

            #pragma unroll
            for (int im = 0; im < 4; im++)
                #pragma unroll
                for (int in = 0; in < 8; in++)
                    mma_bf16(acc[im][in], ah[im], bh[in]);
        }
    }

    // Epilogue: registers -> u16 ranking keys (+bias), one u32 store per pair
    #pragma unroll
    for (int im = 0; im < 4; im++) {
        #pragma unroll
        for (int in = 0; in < 8; in++) {
            const int mr = m0 + wm * 64 + im * 16 + (lane >> 2);
            const int nc = n0 + wn * 64 + in * 8 + (lane & 3) * 2;
            const float2 bv = *(const float2*)(bias + nc);
            const uint32_t k0 = (uint32_t)fkey(acc[im][in][0] + bv.x)
                              | ((uint32_t)fkey(acc[im][in][1] + bv.y) << 16);
            const uint32_t k1 = (uint32_t)fkey(acc[im][in][2] + bv.x)
                              | ((uint32_t)fkey(acc[im][in][3] + bv.y) << 16);
            *(uint32_t*)(g_key + (size_t)mr * D_SAE + nc)       = k0;
            *(uint32_t*)(g_key + (size_t)(mr + 8) * D_SAE + nc) = k1;
        }
    }
}

// ---------------------------------------------------------------------------
// K2: per-row top-NCAND candidate indices via 2-pass byte radix-select on u16
// keys. Keys live in REGISTERS (8 uint4 per thread = 64 keys); smem only for
// the 256-bin histogram -> high occupancy, DRAM-stream bound.
// ---------------------------------------------------------------------------
__global__ __launch_bounds__(256) void topk16_kernel(int k)
{
    __shared__ int hist[256];
    __shared__ uint32_t s_prefix;
    __shared__ int s_krem;
    __shared__ int s_cnt_gt, s_cnt_eq, s_m;

    const int row = blockIdx.x;
    const int tid = threadIdx.x;
    const uint4* src = (const uint4*)(g_key + (size_t)row * D_SAE);

    uint4 kv[8];                       // 64 u16 keys per thread
    #pragma unroll
    for (int i = 0; i < 8; i++)
        kv[i] = src[i * 256 + tid];

    if (tid == 0) { s_prefix = 0u; s_krem = k; }
    hist[tid] = 0;
    __syncthreads();

    // ---- pass 0: high byte ----
    #pragma unroll
    for (int i = 0; i < 8; i++) {
        const uint32_t w[4] = { kv[i].x, kv[i].y, kv[i].z, kv[i].w };
        #pragma unroll
        for (int q = 0; q < 4; q++) {
            atomicAdd(&hist[(w[q] >> 8)  & 0xFFu], 1);
            atomicAdd(&hist[(w[q] >> 24)        ], 1);
        }
    }
    __syncthreads();
    if (tid == 0) {
        int cum = 0, b = 255;
        for (; b > 0; b--) {
            int c = hist[b];
            if (cum + c >= s_krem) break;
            cum += c;
        }
        s_prefix = (uint32_t)b << 8;
        s_krem -= cum;
    }
    __syncthreads();
    const uint32_t hi = s_prefix;
    hist[tid] = 0;
    __syncthreads();

    // ---- pass 1: low byte among keys with matching high byte ----
    #pragma unroll
    for (int i = 0; i < 8; i++) {
        const uint32_t w[4] = { kv[i].x, kv[i].y, kv[i].z, kv[i].w };
        #pragma unroll
        for (int q = 0; q < 4; q++) {
            const uint32_t lo16 = w[q] & 0xFFFFu;
            const uint32_t hi16 = w[q] >> 16;
            if ((lo16 & 0xFF00u) == hi) atomicAdd(&hist[lo16 & 0xFFu], 1);
            if ((hi16 & 0xFF00u) == hi) atomicAdd(&hist[hi16 & 0xFFu], 1);
        }
    }
    __syncthreads();
    if (tid == 0) {
        int cum = 0, b = 255;
        for (; b > 0; b--) {
            int c = hist[b];
            if (cum + c >= s_krem) break;
            cum += c;
        }
        s_prefix = hi | (uint32_t)b;
        s_krem -= cum;
        s_m = k - s_krem;
        s_cnt_gt = 0;
        s_cnt_eq = 0;
    }
    __syncthreads();

    const uint32_t T = s_prefix;   // key of the k-th largest (with ties)
    const int m = s_m;             // count strictly greater than T

    // ---- extraction ----
    #pragma unroll
    for (int i = 0; i < 8; i++) {
        const uint32_t w[4] = { kv[i].x, kv[i].y, kv[i].z, kv[i].w };
        const int base_idx = (i * 256 + tid) * 8;
        #pragma unroll
        for (int q = 0; q < 4; q++) {
            #pragma unroll
            for (int e = 0; e < 2; e++) {
                const uint32_t u = (e == 0) ? (w[q] & 0xFFFFu) : (w[q] >> 16);
                if (u < T) continue;
                int slot = -1;
                if (u > T) {
                    slot = atomicAdd(&s_cnt_gt, 1);
                } else {
                    int p = atomicAdd(&s_cnt_eq, 1);
                    if (m + p < k) slot = m + p;
                }
                if (slot >= 0)
                    g_cidx[(size_t)row * k + slot] = base_idx + q * 2 + e;
            }
        }
    }
}

// ---------------------------------------------------------------------------
// K2b: exact fp32 rescore of NCAND candidates + exact top-64 selection.
// One block per row, 256 threads (8 warps). x row cached in smem; each warp
// computes fp32 dots against g_wt candidate rows (coalesced, ~L2-resident).
// ---------------------------------------------------------------------------
__global__ __launch_bounds__(256) void rescore_kernel(
    const float* __restrict__ x,
    const float* __restrict__ b_enc)
{
    __shared__ float sx[D_IN];
    __shared__ float scval[NCAND];
    __shared__ int   scidx[NCAND];

    const int row  = blockIdx.x;
    const int tid  = threadIdx.x;
    const int lane = tid & 31;
    const int wid  = tid >> 5;

    if (tid < NCAND) scidx[tid] = g_cidx[(size_t)row * NCAND + tid];
    {
        const float4* xr = (const float4*)(x + (size_t)row * D_IN);
        #pragma unroll
        for (int i = 0; i < D_IN / 4 / 256; i++) {
            const int j = i * 256 + tid;
            *(float4*)(sx + j * 4) = xr[j];
        }
    }
    __syncthreads();

    // each warp handles NCAND/8 = 12 candidates
    for (int c = wid; c < NCAND; c += 8) {
        const float* w = g_wt + (size_t)scidx[c] * D_IN;
        float s = 0.0f;
        #pragma unroll
        for (int j0 = 0; j0 < D_IN; j0 += 128) {
            const int j = j0 + lane * 4;
            float4 wv = *(const float4*)(w + j);
            float4 xv = *(const float4*)(sx + j);
            s = fmaf(wv.x, xv.x, s);
            s = fmaf(wv.y, xv.y, s);
            s = fmaf(wv.z, xv.z, s);
            s = fmaf(wv.w, xv.w, s);
        }
        #pragma unroll
        for (int o = 16; o > 0; o >>= 1)
            s += __shfl_xor_sync(0xFFFFFFFFu, s, o);
        if (lane == 0) scval[c] = s + __ldg(b_enc + scidx[c]);
    }
    __syncthreads();

    // exact rank among NCAND (ties: lower index wins, matching jax top_k)
    if (tid < NCAND) {
        const float v = scval[tid];
        const int   ix = scidx[tid];
        int rank = 0;
        #pragma unroll 8
        for (int o = 0; o < NCAND; o++) {
            float ov = scval[o];
            rank += (ov > v) || (ov == v && scidx[o] < ix);
        }
        if (rank < KTOP) {
            g_idx[row * KTOP + rank] = ix;
            g_val[row * KTOP + rank] = fmaxf(v, 0.0f);
        }
    }
}

// ---------------------------------------------------------------------------
// K3: sparse decode (unchanged, verified)
// ---------------------------------------------------------------------------
__global__ __launch_bounds__(512) void decode_kernel(
    const float* __restrict__ Wdec,
    const float* __restrict__ bdec,
    float* __restrict__ out,
    int din, int k)
{
    __shared__ int   sidx[KTOP];
    __shared__ float sval[KTOP];

    const int row = blockIdx.x;
    const int tid = threadIdx.x;
    if (tid < k) {
        sidx[tid] = g_idx[row * k + tid];
        sval[tid] = g_val[row * k + tid];
    }
    __syncthreads();

    const int c = tid * 4;
    if (c < din) {
        float4 acc = *(const float4*)(bdec + c);
        #pragma unroll 8
        for (int j = 0; j < KTOP; j++) {
            float v = sval[j];
            const float4 w = *(const float4*)(Wdec + (size_t)sidx[j] * din + c);
            acc.x = fmaf(v, w.x, acc.x);
            acc.y = fmaf(v, w.y, acc.y);
            acc.z = fmaf(v, w.z, acc.z);
            acc.w = fmaf(v, w.w, acc.w);
        }
        *(float4*)(out + (size_t)row * din + c) = acc;
    }
}

// ---------------------------------------------------------------------------
// Host launch
// ---------------------------------------------------------------------------
extern "C" void kernel_launch(void* const* d_in, const int* in_sizes, int n_in,
                              void* d_out, int out_size)
{
    const float* x     = (const float*)d_in[0];
    const float* W_enc = (const float*)d_in[1];
    const float* W_dec = (const float*)d_in[2];
    const float* b_enc = (const float*)d_in[3];
    const float* b_dec = (const float*)d_in[4];

    const int din  = in_sizes[4];          // 2048
    const int dsae = in_sizes[3];          // 16384
    const int M    = in_sizes[0] / din;    // 8192
    float* out = (float*)d_out;

    // K0: conversions (+ W transpose, fp32 and bf16)
    convert_x_kernel<<<(NROWS * D_IN) / 1024, 256>>>(x);
    dim3 gw(D_SAE / 32, D_IN / 32);
    convert_wt_kernel<<<gw, 256>>>(W_enc);

    // K1: approximate bf16 GEMM -> u16 keys
    cudaFuncSetAttribute(gemm_bf16_kernel,
                         cudaFuncAttributeMaxDynamicSharedMemorySize, GEMM_SMEM);
    const int n_tiles = (M / BM) * (dsae / BN);   // 8192
    gemm_bf16_kernel<<<n_tiles, 128, GEMM_SMEM>>>(b_enc);

    // K2: top-NCAND candidate indices per row (2-pass u16 radix-select)
    topk16_kernel<<<M, 256>>>(NCAND);

    // K2b: exact rescore + exact top-64
    rescore_kernel<<<M, 256>>>(x, b_enc);

    // K3: sparse decode
    decode_kernel<<<M, 512>>>(W_dec, b_dec, out, din, KTOP);
}